// round 1
// baseline (speedup 1.0000x reference)
#include <cuda_runtime.h>

// ---------------------------------------------------------------------------
// NeuralODEBlock: h' = W3 tanh(W2 tanh(W1 (h + t*Wt + bt) + b1) + b2) + b3
// RK4, 10 steps, dt = 0.1.  B=8192, H=512, 2H=1024.
// Baseline: fp32 SIMT GEMM (128x128x16 tiles, 8x8 micro-tile) with fully
// fused epilogues (time-embed on A-load, tanh+bias, RK4 combine).
// ---------------------------------------------------------------------------

#define BATCH  8192
#define HID    512
#define HID2   1024
#define NSTEPS 10

// scratch (device globals: no allocation allowed)
__device__ float g_x1[BATCH * HID2];
__device__ float g_x2[BATCH * HID2];
__device__ float g_kacc[BATCH * HID];
__device__ float g_htmp[BATCH * HID];

__device__ __forceinline__ float fast_tanh(float x) {
    // tanh(x) = 1 - 2/(exp(2x)+1); exp overflow -> +inf -> result 1 (correct),
    // exp underflow -> 0 -> result -1 (correct). ~1e-7 accurate.
    float e = __expf(2.0f * x);
    return 1.0f - __fdividef(2.0f, e + 1.0f);
}

#define BM 128
#define BN 128
#define BK 16
#define TM 8
#define TN 8
#define NTHREADS 256

// MODE 0: out = tanh(A_eff @ W^T + bias), A_eff = A + t*Wt + bt (per-column)
// MODE 1: out = tanh(A @ W^T + bias)
// MODE 2: k = A @ W^T + bias; RK4 epilogue per `stage`:
//   stage 1: kacc = k;        htmp = h + 0.05*k
//   stage 2: kacc += 2k;      htmp = h + 0.05*k
//   stage 3: kacc += 2k;      htmp = h + 0.10*k
//   stage 4: out  = h + (0.1/6)*(kacc + k)      (out aliases h; 1 RMW/elem)
template <int MODE>
__global__ __launch_bounds__(NTHREADS, 2)
void gemm_kernel(const float* __restrict__ A,
                 const float* __restrict__ W,
                 const float* __restrict__ bias,
                 float* __restrict__ out,
                 int N, int K,
                 const float* __restrict__ Wt,
                 const float* __restrict__ bt,
                 float tval,
                 const float* __restrict__ hstate,
                 float* __restrict__ kacc,
                 float* __restrict__ htmp,
                 int stage)
{
    __shared__ float As[BK][BM];
    __shared__ float Bs[BK][BN];

    const int tid = threadIdx.x;
    const int bm = blockIdx.y;
    const int bn = blockIdx.x;

    const float* Ab = A + bm * BM * K;
    const float* Wb = W + bn * BN * K;

    const int ty = tid >> 4;   // 0..15 : M sub-tile
    const int tx = tid & 15;   // 0..15 : N sub-tile

    const int lr = tid >> 2;   // 0..63 : load row base
    const int lc = tid & 3;    // 0..3  : float4 column within BK=16

    float acc[TM][TN];
#pragma unroll
    for (int i = 0; i < TM; i++)
#pragma unroll
        for (int j = 0; j < TN; j++) acc[i][j] = 0.0f;

    for (int k0 = 0; k0 < K; k0 += BK) {
#pragma unroll
        for (int half = 0; half < 2; half++) {
            const int row = lr + half * 64;
            float4 a = *(const float4*)(Ab + row * K + k0 + lc * 4);
            if (MODE == 0) {
                const int c = k0 + lc * 4;
                a.x += tval * Wt[c + 0] + bt[c + 0];
                a.y += tval * Wt[c + 1] + bt[c + 1];
                a.z += tval * Wt[c + 2] + bt[c + 2];
                a.w += tval * Wt[c + 3] + bt[c + 3];
            }
            As[lc * 4 + 0][row] = a.x;
            As[lc * 4 + 1][row] = a.y;
            As[lc * 4 + 2][row] = a.z;
            As[lc * 4 + 3][row] = a.w;

            const float4 w = *(const float4*)(Wb + row * K + k0 + lc * 4);
            Bs[lc * 4 + 0][row] = w.x;
            Bs[lc * 4 + 1][row] = w.y;
            Bs[lc * 4 + 2][row] = w.z;
            Bs[lc * 4 + 3][row] = w.w;
        }
        __syncthreads();

#pragma unroll
        for (int k = 0; k < BK; k++) {
            const float4 a0 = *(const float4*)(&As[k][ty * TM]);
            const float4 a1 = *(const float4*)(&As[k][ty * TM + 4]);
            const float4 b0 = *(const float4*)(&Bs[k][tx * TN]);
            const float4 b1 = *(const float4*)(&Bs[k][tx * TN + 4]);
            const float ra[TM] = {a0.x, a0.y, a0.z, a0.w, a1.x, a1.y, a1.z, a1.w};
            const float rb[TN] = {b0.x, b0.y, b0.z, b0.w, b1.x, b1.y, b1.z, b1.w};
#pragma unroll
            for (int i = 0; i < TM; i++)
#pragma unroll
                for (int j = 0; j < TN; j++)
                    acc[i][j] += ra[i] * rb[j];
        }
        __syncthreads();
    }

    // ---------------- epilogue ----------------
    const int rowbase = bm * BM + ty * TM;
    const int colbase = bn * BN + tx * TN;

#pragma unroll
    for (int i = 0; i < TM; i++) {
        const int r = rowbase + i;
#pragma unroll
        for (int j = 0; j < TN; j += 4) {
            const int c = colbase + j;
            const int idx = r * N + c;
            float4 v;
            v.x = acc[i][j + 0] + bias[c + 0];
            v.y = acc[i][j + 1] + bias[c + 1];
            v.z = acc[i][j + 2] + bias[c + 2];
            v.w = acc[i][j + 3] + bias[c + 3];

            if (MODE <= 1) {
                v.x = fast_tanh(v.x);
                v.y = fast_tanh(v.y);
                v.z = fast_tanh(v.z);
                v.w = fast_tanh(v.w);
                *(float4*)(out + idx) = v;
            } else {
                const float4 hv = *(const float4*)(hstate + idx);
                if (stage == 4) {
                    const float4 ka = *(const float4*)(kacc + idx);
                    const float c6 = 0.1f / 6.0f;
                    float4 o;
                    o.x = hv.x + c6 * (ka.x + v.x);
                    o.y = hv.y + c6 * (ka.y + v.y);
                    o.z = hv.z + c6 * (ka.z + v.z);
                    o.w = hv.w + c6 * (ka.w + v.w);
                    *(float4*)(out + idx) = o;
                } else {
                    const float cf = (stage == 3) ? 0.1f : 0.05f;
                    float4 ht;
                    ht.x = hv.x + cf * v.x;
                    ht.y = hv.y + cf * v.y;
                    ht.z = hv.z + cf * v.z;
                    ht.w = hv.w + cf * v.w;
                    *(float4*)(htmp + idx) = ht;
                    float4 ka;
                    if (stage == 1) {
                        ka = v;
                    } else {
                        ka = *(const float4*)(kacc + idx);
                        ka.x += 2.0f * v.x;
                        ka.y += 2.0f * v.y;
                        ka.z += 2.0f * v.z;
                        ka.w += 2.0f * v.w;
                    }
                    *(float4*)(kacc + idx) = ka;
                }
            }
        }
    }
}

extern "C" void kernel_launch(void* const* d_in, const int* in_sizes, int n_in,
                              void* d_out, int out_size)
{
    const float* h  = (const float*)d_in[0];
    const float* W1 = (const float*)d_in[1];
    const float* b1 = (const float*)d_in[2];
    const float* W2 = (const float*)d_in[3];
    const float* b2 = (const float*)d_in[4];
    const float* W3 = (const float*)d_in[5];
    const float* b3 = (const float*)d_in[6];
    const float* Wt = (const float*)d_in[7];
    const float* bt = (const float*)d_in[8];
    // d_in[9] = n_steps (device scalar); fixed at 10 by the problem shapes.

    float* state = (float*)d_out;

    float *x1, *x2, *kacc, *htmp;
    cudaGetSymbolAddress((void**)&x1,   g_x1);
    cudaGetSymbolAddress((void**)&x2,   g_x2);
    cudaGetSymbolAddress((void**)&kacc, g_kacc);
    cudaGetSymbolAddress((void**)&htmp, g_htmp);

    cudaMemcpyAsync(state, h, (size_t)BATCH * HID * sizeof(float),
                    cudaMemcpyDeviceToDevice);

    const dim3 g1(HID2 / BN, BATCH / BM);  // (8, 64)
    const dim3 g2(HID2 / BN, BATCH / BM);  // (8, 64)
    const dim3 g3(HID  / BN, BATCH / BM);  // (4, 64)

    const float dt = 0.1f;
    for (int s = 0; s < NSTEPS; s++) {
        const float t0 = (float)s * dt;
        const float tv[4] = {t0, t0 + 0.05f, t0 + 0.05f, t0 + 0.1f};
        for (int st = 1; st <= 4; st++) {
            const float* ain = (st == 1) ? state : htmp;
            gemm_kernel<0><<<g1, NTHREADS>>>(ain, W1, b1, x1, HID2, HID,
                                             Wt, bt, tv[st - 1],
                                             nullptr, nullptr, nullptr, 0);
            gemm_kernel<1><<<g2, NTHREADS>>>(x1, W2, b2, x2, HID2, HID2,
                                             nullptr, nullptr, 0.0f,
                                             nullptr, nullptr, nullptr, 0);
            gemm_kernel<2><<<g3, NTHREADS>>>(x2, W3, b3, state, HID, HID2,
                                             nullptr, nullptr, 0.0f,
                                             state, kacc, htmp, st);
        }
    }
}

// round 7
// speedup vs baseline: 2.9638x; 2.9638x over previous
#include <cuda_runtime.h>
#include <cuda_bf16.h>
#include <cstdint>

// ---------------------------------------------------------------------------
// NeuralODEBlock via mma.sync bf16 split-precision GEMMs (base-target safe:
// no tcgen05 -- harness PTX pass targets sm_103 base).
// C = A@W^T = Ah@Wh + Ah@Wl + Al@Wh (bf16 hi/lo split, fp32 accum).
// Fused epilogues: tanh+split (MODE 0), RK4 combine + time-embed + split
// of next GEMM1 input (MODE 1).  FMA-only tanh (no MUFU).
// ---------------------------------------------------------------------------

#define BATCH  8192
#define HID    512
#define HID2   1024
#define NSTEPS 10

#define BM 128
#define BN 128
#define BK 64
#define NTH 512
#define STAGES 3

// byte offsets of tiles within one pipeline stage
#define T_AH 0
#define T_AL 16384
#define T_WH 32768
#define T_WL 49152
#define STAGE_BYTES 65536
#define SMEM_BYTES (STAGES * STAGE_BYTES)   // 196608

// ------------------------- device scratch (no allocs) ----------------------
__device__ __nv_bfloat16 g_x1h[BATCH * HID2];
__device__ __nv_bfloat16 g_x1l[BATCH * HID2];
__device__ __nv_bfloat16 g_x2h[BATCH * HID2];
__device__ __nv_bfloat16 g_x2l[BATCH * HID2];
__device__ __nv_bfloat16 g_ainh[BATCH * HID];
__device__ __nv_bfloat16 g_ainl[BATCH * HID];
__device__ float         g_kacc[BATCH * HID];
__device__ __nv_bfloat16 g_W1h[HID2 * HID],  g_W1l[HID2 * HID];
__device__ __nv_bfloat16 g_W2h[HID2 * HID2], g_W2l[HID2 * HID2];
__device__ __nv_bfloat16 g_W3h[HID * HID2],  g_W3l[HID * HID2];

// ------------------------------ helpers ------------------------------------
__device__ __forceinline__ uint32_t smem_u32(const void* p) {
    uint32_t a;
    asm("{ .reg .u64 t; cvta.to.shared.u64 t, %1; cvt.u32.u64 %0, t; }"
        : "=r"(a) : "l"(p));
    return a;
}

__device__ __forceinline__ void cp16(uint32_t dst, const void* src) {
    asm volatile("cp.async.cg.shared.global [%0], [%1], 16;"
                 :: "r"(dst), "l"(src) : "memory");
}
#define CP_COMMIT() asm volatile("cp.async.commit_group;" ::: "memory")
#define CP_WAIT1()  asm volatile("cp.async.wait_group 1;" ::: "memory")

__device__ __forceinline__ uint32_t sw128(uint32_t off) {
    return off ^ ((off >> 3) & 0x70);
}

#define LDSM4(r, addr)                                                       \
    asm volatile("ldmatrix.sync.aligned.m8n8.x4.shared.b16 {%0,%1,%2,%3}, [%4];" \
        : "=r"((r)[0]), "=r"((r)[1]), "=r"((r)[2]), "=r"((r)[3]) : "r"(addr))

#define MMA(cc, a, b0, b1)                                                   \
    asm volatile("mma.sync.aligned.m16n8k16.row.col.f32.bf16.bf16.f32 "      \
        "{%0,%1,%2,%3}, {%4,%5,%6,%7}, {%8,%9}, {%0,%1,%2,%3};"              \
        : "+f"((cc)[0]), "+f"((cc)[1]), "+f"((cc)[2]), "+f"((cc)[3])         \
        : "r"((a)[0]), "r"((a)[1]), "r"((a)[2]), "r"((a)[3]),                \
          "r"(b0), "r"(b1))

// FMA-only tanh: tanh(x) = 1 - 2/(e^{2x}+1). exp2 via round-trick + poly,
// reciprocal via bit-hack + Newton. ~1e-6 accurate, no MUFU.
__device__ __forceinline__ float fast_tanh(float x) {
    float z = 2.8853900817779268f * x;             // 2x * log2(e)
    z = fminf(fmaxf(z, -38.0f), 38.0f);
    float fz = z + 12582912.0f;                    // 1.5*2^23 round trick
    int   iz = __float_as_int(fz) - 0x4B400000;    // round(z)
    float f  = z - __int2float_rn(iz);             // f in [-0.5, 0.5]
    float p  = 0.0001540353039338161f;
    p = fmaf(p, f, 0.001333355814642844f);
    p = fmaf(p, f, 0.009618129107628477f);
    p = fmaf(p, f, 0.05550410866482158f);
    p = fmaf(p, f, 0.2402265069591007f);
    p = fmaf(p, f, 0.6931471805599453f);
    p = fmaf(p, f, 1.0f);
    float e = __int_as_float(__float_as_int(p) + (iz << 23));   // e^{2x}
    float d = e + 1.0f;
    float r = __int_as_float(0x7EF311C3 - __float_as_int(d));   // ~1/d
    r = r * fmaf(-d, r, 2.0f);
    r = r * fmaf(-d, r, 2.0f);
    r = fmaf(r, fmaf(-d, r, 1.0f), r);
    return fmaf(-2.0f, r, 1.0f);
}

// split (a,b) into packed bf16x2 hi (returned) and lo (out-param)
__device__ __forceinline__ uint32_t split2(float a, float b, uint32_t& lo) {
    __nv_bfloat162 h2 = __floats2bfloat162_rn(a, b);
    uint32_t hu = *(uint32_t*)&h2;
    float ra = __uint_as_float(hu << 16);
    float rb = __uint_as_float(hu & 0xFFFF0000u);
    __nv_bfloat162 l2 = __floats2bfloat162_rn(a - ra, b - rb);
    lo = *(uint32_t*)&l2;
    return hu;
}

// ------------------------------- GEMM kernel --------------------------------
// MODE 0: out{h,l} = split(tanh(A@W^T + bias))
// MODE 1: k = A@W^T + bias; RK4 epilogue per `stage`; writes kacc/state and
//         ain{h,l} = split(next_input + tnext*Wt + bt)
template <int MODE>
__global__ __launch_bounds__(NTH, 1)
void gemm_mma(const __nv_bfloat16* __restrict__ Ah_g, const __nv_bfloat16* __restrict__ Al_g,
              const __nv_bfloat16* __restrict__ Wh_g, const __nv_bfloat16* __restrict__ Wl_g,
              const float* __restrict__ bias, int K, int N, int NC,
              __nv_bfloat16* __restrict__ outh, __nv_bfloat16* __restrict__ outl,
              float* __restrict__ state, float* __restrict__ kacc,
              __nv_bfloat16* __restrict__ ainh, __nv_bfloat16* __restrict__ ainl,
              const float* __restrict__ Wt, const float* __restrict__ bt,
              float tnext, int stage)
{
    extern __shared__ __align__(1024) char smem[];
    const uint32_t sb = smem_u32(smem);
    const int tid = threadIdx.x;
    const int bm = blockIdx.y, bn = blockIdx.x;

    // ---- async tile loader: one 64KB stage = Ah|Al|Wh|Wl, SW128 rows -------
    auto load_chunk = [&](int ci) {
        const uint32_t dstb = sb + (uint32_t)(ci % STAGES) * STAGE_BYTES;
        const int k0 = ci * BK;
#pragma unroll
        for (int q = 0; q < 8; q++) {
            const int flat = q * NTH + tid;
            const int r = flat >> 3;        // 0..511 row-slot
            const int c16 = flat & 7;       // 16B block within 128B row
            const int row = r & 127;
            const __nv_bfloat16* src;
            uint32_t toff;
            if (r < 128)      { src = Ah_g + (size_t)(bm * BM + row) * K; toff = T_AH; }
            else if (r < 256) { src = Al_g + (size_t)(bm * BM + row) * K; toff = T_AL; }
            else if (r < 384) { src = Wh_g + (size_t)(bn * BN + row) * K; toff = T_WH; }
            else              { src = Wl_g + (size_t)(bn * BN + row) * K; toff = T_WL; }
            cp16(dstb + toff + sw128((uint32_t)(row * 128 + c16 * 16)),
                 src + k0 + c16 * 8);
        }
    };

    load_chunk(0); CP_COMMIT();
    load_chunk(1); CP_COMMIT();

    const int l = tid & 31, w = tid >> 5;
    const int wm = w & 3, wn = w >> 2;          // 4x4 warp grid, 32x32 tiles
    const int aRow = l & 15, aKb = l >> 4;      // ldmatrix lane mapping (A)
    const int bRow = (l & 7) | (((l >> 4) & 1) << 3);
    const int bKb  = (l >> 3) & 1;              // (B)

    float acc[2][4][4];
#pragma unroll
    for (int mt = 0; mt < 2; mt++)
#pragma unroll
        for (int nt = 0; nt < 4; nt++)
#pragma unroll
            for (int e = 0; e < 4; e++) acc[mt][nt][e] = 0.0f;

    for (int i = 0; i < NC; i++) {
        CP_WAIT1();
        __syncthreads();
        if (i + 2 < NC) load_chunk(i + 2);
        CP_COMMIT();

        const uint32_t sbase = sb + (uint32_t)(i % STAGES) * STAGE_BYTES;
#pragma unroll
        for (int kk = 0; kk < 4; kk++) {        // 4 x k16 within BK=64
            uint32_t ah[2][4], al[2][4], wh[2][4], wl[2][4];
#pragma unroll
            for (int mt = 0; mt < 2; mt++) {
                const uint32_t off =
                    (uint32_t)((wm * 32 + mt * 16 + aRow) * 128 + (kk * 2 + aKb) * 16);
                LDSM4(ah[mt], sbase + T_AH + sw128(off));
                LDSM4(al[mt], sbase + T_AL + sw128(off));
            }
#pragma unroll
            for (int pr = 0; pr < 2; pr++) {
                const uint32_t off =
                    (uint32_t)((wn * 32 + pr * 16 + bRow) * 128 + (kk * 2 + bKb) * 16);
                LDSM4(wh[pr], sbase + T_WH + sw128(off));
                LDSM4(wl[pr], sbase + T_WL + sw128(off));
            }
#pragma unroll
            for (int nt = 0; nt < 4; nt++) {
                const uint32_t b0h = wh[nt >> 1][(nt & 1) * 2];
                const uint32_t b1h = wh[nt >> 1][(nt & 1) * 2 + 1];
                const uint32_t b0l = wl[nt >> 1][(nt & 1) * 2];
                const uint32_t b1l = wl[nt >> 1][(nt & 1) * 2 + 1];
#pragma unroll
                for (int mt = 0; mt < 2; mt++) {
                    MMA(acc[mt][nt], ah[mt], b0h, b1h);
                    MMA(acc[mt][nt], ah[mt], b0l, b1l);
                    MMA(acc[mt][nt], al[mt], b0h, b1h);
                }
            }
        }
    }

    // ------------------------------ epilogue -------------------------------
    const int rbase  = bm * BM + wm * 32 + (l >> 2);
    const int cbase0 = bn * BN + wn * 32 + (l & 3) * 2;
    const float c6 = 0.1f / 6.0f;

#pragma unroll
    for (int mt = 0; mt < 2; mt++) {
#pragma unroll
        for (int nt = 0; nt < 4; nt++) {
            const int c = cbase0 + nt * 8;
            const float2 bv = *(const float2*)(bias + c);
#pragma unroll
            for (int p = 0; p < 2; p++) {
                const int r = rbase + mt * 16 + p * 8;
                const size_t ib = (size_t)r * N + c;
                float v0 = acc[mt][nt][2 * p + 0] + bv.x;
                float v1 = acc[mt][nt][2 * p + 1] + bv.y;

                if (MODE == 0) {
                    v0 = fast_tanh(v0);
                    v1 = fast_tanh(v1);
                    uint32_t lo, hi = split2(v0, v1, lo);
                    *(uint32_t*)(outh + ib) = hi;
                    *(uint32_t*)(outl + ib) = lo;
                } else {
                    const float2 hv = *(const float2*)(state + ib);
                    float2 av;
                    if (stage == 4) {
                        const float2 ka = *(const float2*)(kacc + ib);
                        av.x = hv.x + c6 * (ka.x + v0);
                        av.y = hv.y + c6 * (ka.y + v1);
                        *(float2*)(state + ib) = av;
                    } else {
                        float2 ka;
                        if (stage == 1) {
                            ka.x = v0; ka.y = v1;
                        } else {
                            ka = *(const float2*)(kacc + ib);
                            ka.x += 2.0f * v0;
                            ka.y += 2.0f * v1;
                        }
                        *(float2*)(kacc + ib) = ka;
                        const float cf = (stage == 3) ? 0.1f : 0.05f;
                        av.x = hv.x + cf * v0;
                        av.y = hv.y + cf * v1;
                    }
                    const float2 wt  = *(const float2*)(Wt + c);
                    const float2 btv = *(const float2*)(bt + c);
                    av.x += tnext * wt.x + btv.x;
                    av.y += tnext * wt.y + btv.y;
                    uint32_t lo, hi = split2(av.x, av.y, lo);
                    *(uint32_t*)(ainh + ib) = hi;
                    *(uint32_t*)(ainl + ib) = lo;
                }
            }
        }
    }
}

// ------------------------- small setup kernels ------------------------------
__global__ void split_arr(const float* __restrict__ src,
                          __nv_bfloat16* __restrict__ h, __nv_bfloat16* __restrict__ l,
                          int n)
{
    int i = blockIdx.x * blockDim.x + threadIdx.x;
    if (i < n) {
        float v = src[i];
        __nv_bfloat16 hi = __float2bfloat16(v);
        h[i] = hi;
        l[i] = __float2bfloat16(v - __bfloat162float(hi));
    }
}

__global__ void init_ain(const float* __restrict__ h0, const float* __restrict__ bt,
                         __nv_bfloat16* __restrict__ ah, __nv_bfloat16* __restrict__ al)
{
    int i = blockIdx.x * blockDim.x + threadIdx.x;
    if (i < BATCH * HID) {
        float v = h0[i] + bt[i & (HID - 1)];   // t=0 -> temb = bt
        __nv_bfloat16 hi = __float2bfloat16(v);
        ah[i] = hi;
        al[i] = __float2bfloat16(v - __bfloat162float(hi));
    }
}

// ------------------------------- launch -------------------------------------
extern "C" void kernel_launch(void* const* d_in, const int* in_sizes, int n_in,
                              void* d_out, int out_size)
{
    const float* h  = (const float*)d_in[0];
    const float* W1 = (const float*)d_in[1];
    const float* b1 = (const float*)d_in[2];
    const float* W2 = (const float*)d_in[3];
    const float* b2 = (const float*)d_in[4];
    const float* W3 = (const float*)d_in[5];
    const float* b3 = (const float*)d_in[6];
    const float* Wt = (const float*)d_in[7];
    const float* bt = (const float*)d_in[8];

    float* state = (float*)d_out;

    __nv_bfloat16 *x1h, *x1l, *x2h, *x2l, *ainh, *ainl;
    __nv_bfloat16 *w1h, *w1l, *w2h, *w2l, *w3h, *w3l;
    float* kacc;
    cudaGetSymbolAddress((void**)&x1h, g_x1h);   cudaGetSymbolAddress((void**)&x1l, g_x1l);
    cudaGetSymbolAddress((void**)&x2h, g_x2h);   cudaGetSymbolAddress((void**)&x2l, g_x2l);
    cudaGetSymbolAddress((void**)&ainh, g_ainh); cudaGetSymbolAddress((void**)&ainl, g_ainl);
    cudaGetSymbolAddress((void**)&kacc, g_kacc);
    cudaGetSymbolAddress((void**)&w1h, g_W1h);   cudaGetSymbolAddress((void**)&w1l, g_W1l);
    cudaGetSymbolAddress((void**)&w2h, g_W2h);   cudaGetSymbolAddress((void**)&w2l, g_W2l);
    cudaGetSymbolAddress((void**)&w3h, g_W3h);   cudaGetSymbolAddress((void**)&w3l, g_W3l);

    cudaFuncSetAttribute(gemm_mma<0>, cudaFuncAttributeMaxDynamicSharedMemorySize, SMEM_BYTES);
    cudaFuncSetAttribute(gemm_mma<1>, cudaFuncAttributeMaxDynamicSharedMemorySize, SMEM_BYTES);

    cudaMemcpyAsync(state, h, (size_t)BATCH * HID * sizeof(float),
                    cudaMemcpyDeviceToDevice);

    split_arr<<<(HID2 * HID  + 255) / 256, 256>>>(W1, w1h, w1l, HID2 * HID);
    split_arr<<<(HID2 * HID2 + 255) / 256, 256>>>(W2, w2h, w2l, HID2 * HID2);
    split_arr<<<(HID * HID2  + 255) / 256, 256>>>(W3, w3h, w3l, HID * HID2);
    init_ain<<<(BATCH * HID + 255) / 256, 256>>>(h, bt, ainh, ainl);

    const dim3 g1(HID2 / BN, BATCH / BM);  // (8, 64)
    const dim3 g2(HID2 / BN, BATCH / BM);  // (8, 64)
    const dim3 g3(HID  / BN, BATCH / BM);  // (4, 64)

    const float dt = 0.1f;
    for (int s = 0; s < NSTEPS; s++) {
        const float t0 = (float)s * dt;
        const float tnext[4] = {t0 + 0.05f, t0 + 0.05f, t0 + 0.1f, t0 + 0.1f};
        for (int st = 1; st <= 4; st++) {
            gemm_mma<0><<<g1, NTH, SMEM_BYTES>>>(ainh, ainl, w1h, w1l, b1,
                                                 HID, HID2, HID / BK,
                                                 x1h, x1l,
                                                 nullptr, nullptr, nullptr, nullptr,
                                                 nullptr, nullptr, 0.0f, 0);
            gemm_mma<0><<<g2, NTH, SMEM_BYTES>>>(x1h, x1l, w2h, w2l, b2,
                                                 HID2, HID2, HID2 / BK,
                                                 x2h, x2l,
                                                 nullptr, nullptr, nullptr, nullptr,
                                                 nullptr, nullptr, 0.0f, 0);
            gemm_mma<1><<<g3, NTH, SMEM_BYTES>>>(x2h, x2l, w3h, w3l, b3,
                                                 HID2, HID, HID2 / BK,
                                                 nullptr, nullptr,
                                                 state, kacc, ainh, ainl,
                                                 Wt, bt, tnext[st - 1], st);
        }
    }
}

// round 8
// speedup vs baseline: 2.9873x; 1.0079x over previous
#include <cuda_runtime.h>
#include <cuda_bf16.h>
#include <cstdint>

// ---------------------------------------------------------------------------
// NeuralODEBlock via mma.sync bf16 split GEMMs (Ah@Wh + Al@Wh + Ah@Wl, fp32
// accum).  R8: 256x128 tiles (less L2 traffic), 2-stage pipeline, GEMM3 in a
// single wave, one fused setup kernel.
// ---------------------------------------------------------------------------

#define BATCH  8192
#define HID    512
#define HID2   1024
#define NSTEPS 10

#define BM 256
#define BN 128
#define BK 64
#define NTH 512

// stage layout: Ah(32K) Al(32K) Wh(16K) Wl(16K) = 96KB
#define T_AH 0
#define T_AL 32768
#define T_WH 65536
#define T_WL 81920
#define STAGE_BYTES 98304
#define SMEM_BYTES (2 * STAGE_BYTES)   // 196608

// ------------------------- device scratch (no allocs) ----------------------
__device__ __nv_bfloat16 g_x1h[BATCH * HID2];
__device__ __nv_bfloat16 g_x1l[BATCH * HID2];
__device__ __nv_bfloat16 g_x2h[BATCH * HID2];
__device__ __nv_bfloat16 g_x2l[BATCH * HID2];
__device__ __nv_bfloat16 g_ainh[BATCH * HID];
__device__ __nv_bfloat16 g_ainl[BATCH * HID];
__device__ float         g_kacc[BATCH * HID];
__device__ __nv_bfloat16 g_W1h[HID2 * HID],  g_W1l[HID2 * HID];
__device__ __nv_bfloat16 g_W2h[HID2 * HID2], g_W2l[HID2 * HID2];
__device__ __nv_bfloat16 g_W3h[HID * HID2],  g_W3l[HID * HID2];

// ------------------------------ helpers ------------------------------------
__device__ __forceinline__ uint32_t smem_u32(const void* p) {
    uint32_t a;
    asm("{ .reg .u64 t; cvta.to.shared.u64 t, %1; cvt.u32.u64 %0, t; }"
        : "=r"(a) : "l"(p));
    return a;
}

__device__ __forceinline__ void cp16(uint32_t dst, const void* src) {
    asm volatile("cp.async.cg.shared.global [%0], [%1], 16;"
                 :: "r"(dst), "l"(src) : "memory");
}
#define CP_COMMIT() asm volatile("cp.async.commit_group;" ::: "memory")
#define CP_WAIT1()  asm volatile("cp.async.wait_group 1;" ::: "memory")

__device__ __forceinline__ uint32_t sw128(uint32_t off) {
    return off ^ ((off >> 3) & 0x70);
}

#define LDSM4(r, addr)                                                       \
    asm volatile("ldmatrix.sync.aligned.m8n8.x4.shared.b16 {%0,%1,%2,%3}, [%4];" \
        : "=r"((r)[0]), "=r"((r)[1]), "=r"((r)[2]), "=r"((r)[3]) : "r"(addr))

#define MMA(cc, a, b0, b1)                                                   \
    asm volatile("mma.sync.aligned.m16n8k16.row.col.f32.bf16.bf16.f32 "      \
        "{%0,%1,%2,%3}, {%4,%5,%6,%7}, {%8,%9}, {%0,%1,%2,%3};"              \
        : "+f"((cc)[0]), "+f"((cc)[1]), "+f"((cc)[2]), "+f"((cc)[3])         \
        : "r"((a)[0]), "r"((a)[1]), "r"((a)[2]), "r"((a)[3]),                \
          "r"(b0), "r"(b1))

// FMA-only tanh: tanh(x) = 1 - 2/(e^{2x}+1). ~1e-6 accurate, no MUFU.
__device__ __forceinline__ float fast_tanh(float x) {
    float z = 2.8853900817779268f * x;             // 2x * log2(e)
    z = fminf(fmaxf(z, -38.0f), 38.0f);
    float fz = z + 12582912.0f;                    // 1.5*2^23 round trick
    int   iz = __float_as_int(fz) - 0x4B400000;    // round(z)
    float f  = z - __int2float_rn(iz);             // f in [-0.5, 0.5]
    float p  = 0.0001540353039338161f;
    p = fmaf(p, f, 0.001333355814642844f);
    p = fmaf(p, f, 0.009618129107628477f);
    p = fmaf(p, f, 0.05550410866482158f);
    p = fmaf(p, f, 0.2402265069591007f);
    p = fmaf(p, f, 0.6931471805599453f);
    p = fmaf(p, f, 1.0f);
    float e = __int_as_float(__float_as_int(p) + (iz << 23));   // e^{2x}
    float d = e + 1.0f;
    float r = __int_as_float(0x7EF311C3 - __float_as_int(d));   // ~1/d
    r = r * fmaf(-d, r, 2.0f);
    r = r * fmaf(-d, r, 2.0f);
    r = fmaf(r, fmaf(-d, r, 1.0f), r);
    return fmaf(-2.0f, r, 1.0f);
}

// split (a,b) into packed bf16x2 hi (returned) and lo (out-param)
__device__ __forceinline__ uint32_t split2(float a, float b, uint32_t& lo) {
    __nv_bfloat162 h2 = __floats2bfloat162_rn(a, b);
    uint32_t hu = *(uint32_t*)&h2;
    float ra = __uint_as_float(hu << 16);
    float rb = __uint_as_float(hu & 0xFFFF0000u);
    __nv_bfloat162 l2 = __floats2bfloat162_rn(a - ra, b - rb);
    lo = *(uint32_t*)&l2;
    return hu;
}

// ------------------------------- GEMM kernel --------------------------------
// MODE 0: out{h,l} = split(tanh(A@W^T + bias))
// MODE 1: k = A@W^T + bias; RK4 epilogue per `stage`; writes kacc/state and
//         ain{h,l} = split(next_input + tnext*Wt + bt)
template <int MODE>
__global__ __launch_bounds__(NTH)
void gemm_mma(const __nv_bfloat16* __restrict__ Ah_g, const __nv_bfloat16* __restrict__ Al_g,
              const __nv_bfloat16* __restrict__ Wh_g, const __nv_bfloat16* __restrict__ Wl_g,
              const float* __restrict__ bias, int K, int N, int NC,
              __nv_bfloat16* __restrict__ outh, __nv_bfloat16* __restrict__ outl,
              float* __restrict__ state, float* __restrict__ kacc,
              __nv_bfloat16* __restrict__ ainh, __nv_bfloat16* __restrict__ ainl,
              const float* __restrict__ Wt, const float* __restrict__ bt,
              float tnext, int stage)
{
    extern __shared__ __align__(1024) char smem[];
    const uint32_t sb = smem_u32(smem);
    const int tid = threadIdx.x;
    const int bm = blockIdx.y, bn = blockIdx.x;

    // ---- loader: one 96KB stage = Ah(256r)|Al(256r)|Wh(128r)|Wl(128r) ------
    auto load_chunk = [&](int ci) {
        const uint32_t dstb = sb + (uint32_t)(ci & 1) * STAGE_BYTES;
        const int k0 = ci * BK;
#pragma unroll
        for (int q = 0; q < 12; q++) {
            const int flat = q * NTH + tid;   // 0..6143
            const int rs = flat >> 3;         // 0..767 row-slot
            const int c16 = flat & 7;         // 16B block within 128B row
            const __nv_bfloat16* src;
            uint32_t toff;
            int row;
            if (rs < 512) {
                row = rs & 255;
                src = (rs < 256 ? Ah_g : Al_g) + (size_t)(bm * BM + row) * K;
                toff = (rs < 256 ? T_AH : T_AL);
            } else {
                row = rs & 127;
                src = (rs < 640 ? Wh_g : Wl_g) + (size_t)(bn * BN + row) * K;
                toff = (rs < 640 ? T_WH : T_WL);
            }
            cp16(dstb + toff + sw128((uint32_t)(row * 128 + c16 * 16)),
                 src + k0 + c16 * 8);
        }
    };

    load_chunk(0); CP_COMMIT();
    load_chunk(1); CP_COMMIT();

    const int l = tid & 31, w = tid >> 5;
    const int wm = w >> 1, wn = w & 1;          // 8x2 warp grid, 32x64 tiles
    const int aRow = l & 15, aKb = l >> 4;      // ldmatrix lane mapping (A)
    const int bRow = (l & 7) | (((l >> 4) & 1) << 3);
    const int bKb  = (l >> 3) & 1;              // (B)

    float acc[2][8][4];
#pragma unroll
    for (int mt = 0; mt < 2; mt++)
#pragma unroll
        for (int nf = 0; nf < 8; nf++)
#pragma unroll
            for (int e = 0; e < 4; e++) acc[mt][nf][e] = 0.0f;

    for (int i = 0; i < NC; i++) {
        CP_WAIT1();            // chunk i complete (empty-commit trick keeps this valid)
        __syncthreads();

        const uint32_t sbase = sb + (uint32_t)(i & 1) * STAGE_BYTES;
#pragma unroll
        for (int kk = 0; kk < 4; kk++) {        // 4 x k16 within BK=64
            uint32_t ah[2][4], al[2][4], wb[4][4];
#pragma unroll
            for (int mt = 0; mt < 2; mt++) {
                const uint32_t off =
                    (uint32_t)((wm * 32 + mt * 16 + aRow) * 128 + (kk * 2 + aKb) * 16);
                LDSM4(ah[mt], sbase + T_AH + sw128(off));
                LDSM4(al[mt], sbase + T_AL + sw128(off));
            }
#pragma unroll
            for (int pr = 0; pr < 4; pr++) {
                const uint32_t offb =
                    (uint32_t)((wn * 64 + pr * 16 + bRow) * 128 + (kk * 2 + bKb) * 16);
                LDSM4(wb[pr], sbase + T_WH + sw128(offb));
            }
#pragma unroll
            for (int nf = 0; nf < 8; nf++) {
                const uint32_t b0 = wb[nf >> 1][(nf & 1) * 2];
                const uint32_t b1 = wb[nf >> 1][(nf & 1) * 2 + 1];
                MMA(acc[0][nf], ah[0], b0, b1);
                MMA(acc[1][nf], ah[1], b0, b1);
                MMA(acc[0][nf], al[0], b0, b1);
                MMA(acc[1][nf], al[1], b0, b1);
            }
#pragma unroll
            for (int pr = 0; pr < 4; pr++) {
                const uint32_t offb =
                    (uint32_t)((wn * 64 + pr * 16 + bRow) * 128 + (kk * 2 + bKb) * 16);
                LDSM4(wb[pr], sbase + T_WL + sw128(offb));
            }
#pragma unroll
            for (int nf = 0; nf < 8; nf++) {
                const uint32_t b0 = wb[nf >> 1][(nf & 1) * 2];
                const uint32_t b1 = wb[nf >> 1][(nf & 1) * 2 + 1];
                MMA(acc[0][nf], ah[0], b0, b1);
                MMA(acc[1][nf], ah[1], b0, b1);
            }
        }

        __syncthreads();       // everyone done reading buf i&1 before reuse
        if (i + 2 < NC) load_chunk(i + 2);
        CP_COMMIT();           // always commit (possibly empty group)
    }

    // ------------------------------ epilogue -------------------------------
    const int rbase  = bm * BM + wm * 32 + (l >> 2);
    const int cbase0 = bn * BN + wn * 64 + (l & 3) * 2;
    const float c6 = 0.1f / 6.0f;

#pragma unroll
    for (int mt = 0; mt < 2; mt++) {
#pragma unroll
        for (int nf = 0; nf < 8; nf++) {
            const int c = cbase0 + nf * 8;
            const float2 bv = *(const float2*)(bias + c);
#pragma unroll
            for (int p = 0; p < 2; p++) {
                const int r = rbase + mt * 16 + p * 8;
                const size_t ib = (size_t)r * N + c;
                float v0 = acc[mt][nf][2 * p + 0] + bv.x;
                float v1 = acc[mt][nf][2 * p + 1] + bv.y;

                if (MODE == 0) {
                    v0 = fast_tanh(v0);
                    v1 = fast_tanh(v1);
                    uint32_t lo, hi = split2(v0, v1, lo);
                    *(uint32_t*)(outh + ib) = hi;
                    *(uint32_t*)(outl + ib) = lo;
                } else {
                    const float2 hv = *(const float2*)(state + ib);
                    float2 av;
                    if (stage == 4) {
                        const float2 ka = *(const float2*)(kacc + ib);
                        av.x = hv.x + c6 * (ka.x + v0);
                        av.y = hv.y + c6 * (ka.y + v1);
                        *(float2*)(state + ib) = av;
                    } else {
                        float2 ka;
                        if (stage == 1) {
                            ka.x = v0; ka.y = v1;
                        } else {
                            ka = *(const float2*)(kacc + ib);
                            ka.x += 2.0f * v0;
                            ka.y += 2.0f * v1;
                        }
                        *(float2*)(kacc + ib) = ka;
                        const float cf = (stage == 3) ? 0.1f : 0.05f;
                        av.x = hv.x + cf * v0;
                        av.y = hv.y + cf * v1;
                    }
                    const float2 wt  = *(const float2*)(Wt + c);
                    const float2 btv = *(const float2*)(bt + c);
                    av.x += tnext * wt.x + btv.x;
                    av.y += tnext * wt.y + btv.y;
                    uint32_t lo, hi = split2(av.x, av.y, lo);
                    *(uint32_t*)(ainh + ib) = hi;
                    *(uint32_t*)(ainl + ib) = lo;
                }
            }
        }
    }
}

// --------------------- fused setup kernel (one launch) ----------------------
__global__ void setup_all(const float* __restrict__ h0,
                          const float* __restrict__ W1, const float* __restrict__ W2,
                          const float* __restrict__ W3, const float* __restrict__ bt)
{
    const int i = blockIdx.x * blockDim.x + threadIdx.x;

    if (i < BATCH * HID) {                       // init GEMM1 input at t=0
        float v = h0[i] + bt[i & (HID - 1)];
        __nv_bfloat16 hi = __float2bfloat16(v);
        g_ainh[i] = hi;
        g_ainl[i] = __float2bfloat16(v - __bfloat162float(hi));
    }
    if (i < HID2 * HID2) {                       // W2 split
        float v = W2[i];
        __nv_bfloat16 hi = __float2bfloat16(v);
        g_W2h[i] = hi;
        g_W2l[i] = __float2bfloat16(v - __bfloat162float(hi));
    }
    if (i < HID2 * HID) {                        // W1 + W3 splits
        float v = W1[i];
        __nv_bfloat16 hi = __float2bfloat16(v);
        g_W1h[i] = hi;
        g_W1l[i] = __float2bfloat16(v - __bfloat162float(hi));
        float u = W3[i];
        __nv_bfloat16 hj = __float2bfloat16(u);
        g_W3h[i] = hj;
        g_W3l[i] = __float2bfloat16(u - __bfloat162float(hj));
    }
}

// ------------------------------- launch -------------------------------------
extern "C" void kernel_launch(void* const* d_in, const int* in_sizes, int n_in,
                              void* d_out, int out_size)
{
    const float* h  = (const float*)d_in[0];
    const float* W1 = (const float*)d_in[1];
    const float* b1 = (const float*)d_in[2];
    const float* W2 = (const float*)d_in[3];
    const float* b2 = (const float*)d_in[4];
    const float* W3 = (const float*)d_in[5];
    const float* b3 = (const float*)d_in[6];
    const float* Wt = (const float*)d_in[7];
    const float* bt = (const float*)d_in[8];

    float* state = (float*)d_out;

    __nv_bfloat16 *x1h, *x1l, *x2h, *x2l, *ainh, *ainl;
    __nv_bfloat16 *w1h, *w1l, *w2h, *w2l, *w3h, *w3l;
    float* kacc;
    cudaGetSymbolAddress((void**)&x1h, g_x1h);   cudaGetSymbolAddress((void**)&x1l, g_x1l);
    cudaGetSymbolAddress((void**)&x2h, g_x2h);   cudaGetSymbolAddress((void**)&x2l, g_x2l);
    cudaGetSymbolAddress((void**)&ainh, g_ainh); cudaGetSymbolAddress((void**)&ainl, g_ainl);
    cudaGetSymbolAddress((void**)&kacc, g_kacc);
    cudaGetSymbolAddress((void**)&w1h, g_W1h);   cudaGetSymbolAddress((void**)&w1l, g_W1l);
    cudaGetSymbolAddress((void**)&w2h, g_W2h);   cudaGetSymbolAddress((void**)&w2l, g_W2l);
    cudaGetSymbolAddress((void**)&w3h, g_W3h);   cudaGetSymbolAddress((void**)&w3l, g_W3l);

    cudaFuncSetAttribute(gemm_mma<0>, cudaFuncAttributeMaxDynamicSharedMemorySize, SMEM_BYTES);
    cudaFuncSetAttribute(gemm_mma<1>, cudaFuncAttributeMaxDynamicSharedMemorySize, SMEM_BYTES);

    cudaMemcpyAsync(state, h, (size_t)BATCH * HID * sizeof(float),
                    cudaMemcpyDeviceToDevice);

    setup_all<<<(BATCH * HID + 255) / 256, 256>>>(h, W1, W2, W3, bt);

    const dim3 g1(HID2 / BN, BATCH / BM);  // (8, 32) = 256 CTAs
    const dim3 g2(HID2 / BN, BATCH / BM);  // (8, 32) = 256 CTAs
    const dim3 g3(HID  / BN, BATCH / BM);  // (4, 32) = 128 CTAs (single wave)

    const float dt = 0.1f;
    for (int s = 0; s < NSTEPS; s++) {
        const float t0 = (float)s * dt;
        const float tnext[4] = {t0 + 0.05f, t0 + 0.05f, t0 + 0.1f, t0 + 0.1f};
        for (int st = 1; st <= 4; st++) {
            gemm_mma<0><<<g1, NTH, SMEM_BYTES>>>(ainh, ainl, w1h, w1l, b1,
                                                 HID, HID2, HID / BK,
                                                 x1h, x1l,
                                                 nullptr, nullptr, nullptr, nullptr,
                                                 nullptr, nullptr, 0.0f, 0);
            gemm_mma<0><<<g2, NTH, SMEM_BYTES>>>(x1h, x1l, w2h, w2l, b2,
                                                 HID2, HID2, HID2 / BK,
                                                 x2h, x2l,
                                                 nullptr, nullptr, nullptr, nullptr,
                                                 nullptr, nullptr, 0.0f, 0);
            gemm_mma<1><<<g3, NTH, SMEM_BYTES>>>(x2h, x2l, w3h, w3l, b3,
                                                 HID2, HID, HID2 / BK,
                                                 nullptr, nullptr,
                                                 state, kacc, ainh, ainl,
                                                 Wt, bt, tnext[st - 1], st);
        }
    }
}

// round 12
// speedup vs baseline: 3.4990x; 1.1713x over previous
#include <cuda_runtime.h>
#include <cuda_bf16.h>
#include <cstdint>

// ---------------------------------------------------------------------------
// NeuralODEBlock via mma.sync bf16 split GEMMs (Ah@Wh + Al@Wh + Ah@Wl, fp32
// accum).  R9: 128x64 tiles, 256 threads, 2 CTAs/SM (cross-CTA overlap hides
// barriers/epilogues), 2-stage cp.async pipeline.
// ---------------------------------------------------------------------------

#define BATCH  8192
#define HID    512
#define HID2   1024
#define NSTEPS 10

#define BM 128
#define BN 64
#define BK 64
#define NTH 256

// stage layout: Ah(16K) Al(16K) Wh(8K) Wl(8K) = 48KB
#define T_AH 0
#define T_AL 16384
#define T_WH 32768
#define T_WL 40960
#define STAGE_BYTES 49152
#define SMEM_BYTES (2 * STAGE_BYTES)   // 98304 per CTA; 2 CTAs/SM = 192KB

// ------------------------- device scratch (no allocs) ----------------------
__device__ __nv_bfloat16 g_x1h[BATCH * HID2];
__device__ __nv_bfloat16 g_x1l[BATCH * HID2];
__device__ __nv_bfloat16 g_x2h[BATCH * HID2];
__device__ __nv_bfloat16 g_x2l[BATCH * HID2];
__device__ __nv_bfloat16 g_ainh[BATCH * HID];
__device__ __nv_bfloat16 g_ainl[BATCH * HID];
__device__ float         g_kacc[BATCH * HID];
__device__ __nv_bfloat16 g_W1h[HID2 * HID],  g_W1l[HID2 * HID];
__device__ __nv_bfloat16 g_W2h[HID2 * HID2], g_W2l[HID2 * HID2];
__device__ __nv_bfloat16 g_W3h[HID * HID2],  g_W3l[HID * HID2];

// ------------------------------ helpers ------------------------------------
__device__ __forceinline__ uint32_t smem_u32(const void* p) {
    uint32_t a;
    asm("{ .reg .u64 t; cvta.to.shared.u64 t, %1; cvt.u32.u64 %0, t; }"
        : "=r"(a) : "l"(p));
    return a;
}

__device__ __forceinline__ void cp16(uint32_t dst, const void* src) {
    asm volatile("cp.async.cg.shared.global [%0], [%1], 16;"
                 :: "r"(dst), "l"(src) : "memory");
}
#define CP_COMMIT() asm volatile("cp.async.commit_group;" ::: "memory")
#define CP_WAIT1()  asm volatile("cp.async.wait_group 1;" ::: "memory")

__device__ __forceinline__ uint32_t sw128(uint32_t off) {
    return off ^ ((off >> 3) & 0x70);
}

#define LDSM4(r, addr)                                                       \
    asm volatile("ldmatrix.sync.aligned.m8n8.x4.shared.b16 {%0,%1,%2,%3}, [%4];" \
        : "=r"((r)[0]), "=r"((r)[1]), "=r"((r)[2]), "=r"((r)[3]) : "r"(addr))

#define MMA(cc, a, b0, b1)                                                   \
    asm volatile("mma.sync.aligned.m16n8k16.row.col.f32.bf16.bf16.f32 "      \
        "{%0,%1,%2,%3}, {%4,%5,%6,%7}, {%8,%9}, {%0,%1,%2,%3};"              \
        : "+f"((cc)[0]), "+f"((cc)[1]), "+f"((cc)[2]), "+f"((cc)[3])         \
        : "r"((a)[0]), "r"((a)[1]), "r"((a)[2]), "r"((a)[3]),                \
          "r"(b0), "r"(b1))

// FMA-only tanh: tanh(x) = 1 - 2/(e^{2x}+1). ~1e-6 accurate, no MUFU.
__device__ __forceinline__ float fast_tanh(float x) {
    float z = 2.8853900817779268f * x;             // 2x * log2(e)
    z = fminf(fmaxf(z, -38.0f), 38.0f);
    float fz = z + 12582912.0f;                    // 1.5*2^23 round trick
    int   iz = __float_as_int(fz) - 0x4B400000;    // round(z)
    float f  = z - __int2float_rn(iz);             // f in [-0.5, 0.5]
    float p  = 0.0001540353039338161f;
    p = fmaf(p, f, 0.001333355814642844f);
    p = fmaf(p, f, 0.009618129107628477f);
    p = fmaf(p, f, 0.05550410866482158f);
    p = fmaf(p, f, 0.2402265069591007f);
    p = fmaf(p, f, 0.6931471805599453f);
    p = fmaf(p, f, 1.0f);
    float e = __int_as_float(__float_as_int(p) + (iz << 23));   // e^{2x}
    float d = e + 1.0f;
    float r = __int_as_float(0x7EF311C3 - __float_as_int(d));   // ~1/d
    r = r * fmaf(-d, r, 2.0f);
    r = r * fmaf(-d, r, 2.0f);
    r = fmaf(r, fmaf(-d, r, 1.0f), r);
    return fmaf(-2.0f, r, 1.0f);
}

// split (a,b) into packed bf16x2 hi (returned) and lo (out-param)
__device__ __forceinline__ uint32_t split2(float a, float b, uint32_t& lo) {
    __nv_bfloat162 h2 = __floats2bfloat162_rn(a, b);
    uint32_t hu = *(uint32_t*)&h2;
    float ra = __uint_as_float(hu << 16);
    float rb = __uint_as_float(hu & 0xFFFF0000u);
    __nv_bfloat162 l2 = __floats2bfloat162_rn(a - ra, b - rb);
    lo = *(uint32_t*)&l2;
    return hu;
}

// ------------------------------- GEMM kernel --------------------------------
// MODE 0: out{h,l} = split(tanh(A@W^T + bias))
// MODE 1: k = A@W^T + bias; RK4 epilogue per `stage`; writes kacc/state and
//         ain{h,l} = split(next_input + tnext*Wt + bt)
template <int MODE>
__global__ __launch_bounds__(NTH, 2)
void gemm_mma(const __nv_bfloat16* __restrict__ Ah_g, const __nv_bfloat16* __restrict__ Al_g,
              const __nv_bfloat16* __restrict__ Wh_g, const __nv_bfloat16* __restrict__ Wl_g,
              const float* __restrict__ bias, int K, int N, int NC,
              __nv_bfloat16* __restrict__ outh, __nv_bfloat16* __restrict__ outl,
              float* __restrict__ state, float* __restrict__ kacc,
              __nv_bfloat16* __restrict__ ainh, __nv_bfloat16* __restrict__ ainl,
              const float* __restrict__ Wt, const float* __restrict__ bt,
              float tnext, int stage)
{
    extern __shared__ __align__(1024) char smem[];
    const uint32_t sb = smem_u32(smem);
    const int tid = threadIdx.x;
    const int bm = blockIdx.y, bn = blockIdx.x;

    // ---- loader: one 48KB stage = Ah(128r)|Al(128r)|Wh(64r)|Wl(64r) --------
    auto load_chunk = [&](int ci) {
        const uint32_t dstb = sb + (uint32_t)(ci & 1) * STAGE_BYTES;
        const int k0 = ci * BK;
#pragma unroll
        for (int q = 0; q < 12; q++) {
            const int flat = q * NTH + tid;   // 0..3071
            const int rs = flat >> 3;         // 0..383 row-slot
            const int c16 = flat & 7;         // 16B block within 128B row
            const __nv_bfloat16* src;
            uint32_t toff;
            int row;
            if (rs < 256) {
                row = rs & 127;
                src = (rs < 128 ? Ah_g : Al_g) + (size_t)(bm * BM + row) * K;
                toff = (rs < 128 ? T_AH : T_AL);
            } else {
                row = rs & 63;
                src = (rs < 320 ? Wh_g : Wl_g) + (size_t)(bn * BN + row) * K;
                toff = (rs < 320 ? T_WH : T_WL);
            }
            cp16(dstb + toff + sw128((uint32_t)(row * 128 + c16 * 16)),
                 src + k0 + c16 * 8);
        }
    };

    load_chunk(0); CP_COMMIT();
    load_chunk(1); CP_COMMIT();

    const int l = tid & 31, w = tid >> 5;
    const int wm = w >> 1, wn = w & 1;          // 4x2 warp grid, 32x32 tiles
    const int aRow = l & 15, aKb = l >> 4;      // ldmatrix lane mapping (A)
    const int bRow = (l & 7) | (((l >> 4) & 1) << 3);
    const int bKb  = (l >> 3) & 1;              // (B)

    float acc[2][4][4];
#pragma unroll
    for (int mt = 0; mt < 2; mt++)
#pragma unroll
        for (int nf = 0; nf < 4; nf++)
#pragma unroll
            for (int e = 0; e < 4; e++) acc[mt][nf][e] = 0.0f;

    for (int i = 0; i < NC; i++) {
        CP_WAIT1();            // chunk i resident (empty-commit trick)
        __syncthreads();

        const uint32_t sbase = sb + (uint32_t)(i & 1) * STAGE_BYTES;
#pragma unroll
        for (int kk = 0; kk < 4; kk++) {        // 4 x k16 within BK=64
            uint32_t ah[2][4], al[2][4], wh[2][4], wl[2][4];
#pragma unroll
            for (int mt = 0; mt < 2; mt++) {
                const uint32_t off =
                    (uint32_t)((wm * 32 + mt * 16 + aRow) * 128 + (kk * 2 + aKb) * 16);
                LDSM4(ah[mt], sbase + T_AH + sw128(off));
                LDSM4(al[mt], sbase + T_AL + sw128(off));
            }
#pragma unroll
            for (int pr = 0; pr < 2; pr++) {
                const uint32_t offb =
                    (uint32_t)((wn * 32 + pr * 16 + bRow) * 128 + (kk * 2 + bKb) * 16);
                LDSM4(wh[pr], sbase + T_WH + sw128(offb));
                LDSM4(wl[pr], sbase + T_WL + sw128(offb));
            }
#pragma unroll
            for (int nf = 0; nf < 4; nf++) {
                const uint32_t b0h = wh[nf >> 1][(nf & 1) * 2];
                const uint32_t b1h = wh[nf >> 1][(nf & 1) * 2 + 1];
                const uint32_t b0l = wl[nf >> 1][(nf & 1) * 2];
                const uint32_t b1l = wl[nf >> 1][(nf & 1) * 2 + 1];
                MMA(acc[0][nf], ah[0], b0h, b1h);
                MMA(acc[1][nf], ah[1], b0h, b1h);
                MMA(acc[0][nf], al[0], b0h, b1h);
                MMA(acc[1][nf], al[1], b0h, b1h);
                MMA(acc[0][nf], ah[0], b0l, b1l);
                MMA(acc[1][nf], ah[1], b0l, b1l);
            }
        }

        __syncthreads();       // all reads of buf i&1 done before reuse
        if (i + 2 < NC) load_chunk(i + 2);
        CP_COMMIT();           // always commit (possibly empty group)
    }

    // ------------------------------ epilogue -------------------------------
    const int rbase  = bm * BM + wm * 32 + (l >> 2);
    const int cbase0 = bn * BN + wn * 32 + (l & 3) * 2;
    const float c6 = 0.1f / 6.0f;

#pragma unroll
    for (int mt = 0; mt < 2; mt++) {
#pragma unroll
        for (int nf = 0; nf < 4; nf++) {
            const int c = cbase0 + nf * 8;
            const float2 bv = *(const float2*)(bias + c);
#pragma unroll
            for (int p = 0; p < 2; p++) {
                const int r = rbase + mt * 16 + p * 8;
                const size_t ib = (size_t)r * N + c;
                float v0 = acc[mt][nf][2 * p + 0] + bv.x;
                float v1 = acc[mt][nf][2 * p + 1] + bv.y;

                if (MODE == 0) {
                    v0 = fast_tanh(v0);
                    v1 = fast_tanh(v1);
                    uint32_t lo, hi = split2(v0, v1, lo);
                    *(uint32_t*)(outh + ib) = hi;
                    *(uint32_t*)(outl + ib) = lo;
                } else {
                    const float2 hv = *(const float2*)(state + ib);
                    float2 av;
                    if (stage == 4) {
                        const float2 ka = *(const float2*)(kacc + ib);
                        av.x = hv.x + c6 * (ka.x + v0);
                        av.y = hv.y + c6 * (ka.y + v1);
                        *(float2*)(state + ib) = av;
                    } else {
                        float2 ka;
                        if (stage == 1) {
                            ka.x = v0; ka.y = v1;
                        } else {
                            ka = *(const float2*)(kacc + ib);
                            ka.x += 2.0f * v0;
                            ka.y += 2.0f * v1;
                        }
                        *(float2*)(kacc + ib) = ka;
                        const float cf = (stage == 3) ? 0.1f : 0.05f;
                        av.x = hv.x + cf * v0;
                        av.y = hv.y + cf * v1;
                    }
                    const float2 wt  = *(const float2*)(Wt + c);
                    const float2 btv = *(const float2*)(bt + c);
                    av.x += tnext * wt.x + btv.x;
                    av.y += tnext * wt.y + btv.y;
                    uint32_t lo, hi = split2(av.x, av.y, lo);
                    *(uint32_t*)(ainh + ib) = hi;
                    *(uint32_t*)(ainl + ib) = lo;
                }
            }
        }
    }
}

// --------------------- fused setup kernel (one launch) ----------------------
__global__ void setup_all(const float* __restrict__ h0,
                          const float* __restrict__ W1, const float* __restrict__ W2,
                          const float* __restrict__ W3, const float* __restrict__ bt)
{
    const int i = blockIdx.x * blockDim.x + threadIdx.x;

    if (i < BATCH * HID) {                       // init GEMM1 input at t=0
        float v = h0[i] + bt[i & (HID - 1)];
        __nv_bfloat16 hi = __float2bfloat16(v);
        g_ainh[i] = hi;
        g_ainl[i] = __float2bfloat16(v - __bfloat162float(hi));
    }
    if (i < HID2 * HID2) {                       // W2 split
        float v = W2[i];
        __nv_bfloat16 hi = __float2bfloat16(v);
        g_W2h[i] = hi;
        g_W2l[i] = __float2bfloat16(v - __bfloat162float(hi));
    }
    if (i < HID2 * HID) {                        // W1 + W3 splits
        float v = W1[i];
        __nv_bfloat16 hi = __float2bfloat16(v);
        g_W1h[i] = hi;
        g_W1l[i] = __float2bfloat16(v - __bfloat162float(hi));
        float u = W3[i];
        __nv_bfloat16 hj = __float2bfloat16(u);
        g_W3h[i] = hj;
        g_W3l[i] = __float2bfloat16(u - __bfloat162float(hj));
    }
}

// ------------------------------- launch -------------------------------------
extern "C" void kernel_launch(void* const* d_in, const int* in_sizes, int n_in,
                              void* d_out, int out_size)
{
    const float* h  = (const float*)d_in[0];
    const float* W1 = (const float*)d_in[1];
    const float* b1 = (const float*)d_in[2];
    const float* W2 = (const float*)d_in[3];
    const float* b2 = (const float*)d_in[4];
    const float* W3 = (const float*)d_in[5];
    const float* b3 = (const float*)d_in[6];
    const float* Wt = (const float*)d_in[7];
    const float* bt = (const float*)d_in[8];

    float* state = (float*)d_out;

    __nv_bfloat16 *x1h, *x1l, *x2h, *x2l, *ainh, *ainl;
    __nv_bfloat16 *w1h, *w1l, *w2h, *w2l, *w3h, *w3l;
    float* kacc;
    cudaGetSymbolAddress((void**)&x1h, g_x1h);   cudaGetSymbolAddress((void**)&x1l, g_x1l);
    cudaGetSymbolAddress((void**)&x2h, g_x2h);   cudaGetSymbolAddress((void**)&x2l, g_x2l);
    cudaGetSymbolAddress((void**)&ainh, g_ainh); cudaGetSymbolAddress((void**)&ainl, g_ainl);
    cudaGetSymbolAddress((void**)&kacc, g_kacc);
    cudaGetSymbolAddress((void**)&w1h, g_W1h);   cudaGetSymbolAddress((void**)&w1l, g_W1l);
    cudaGetSymbolAddress((void**)&w2h, g_W2h);   cudaGetSymbolAddress((void**)&w2l, g_W2l);
    cudaGetSymbolAddress((void**)&w3h, g_W3h);   cudaGetSymbolAddress((void**)&w3l, g_W3l);

    cudaFuncSetAttribute(gemm_mma<0>, cudaFuncAttributeMaxDynamicSharedMemorySize, SMEM_BYTES);
    cudaFuncSetAttribute(gemm_mma<1>, cudaFuncAttributeMaxDynamicSharedMemorySize, SMEM_BYTES);

    cudaMemcpyAsync(state, h, (size_t)BATCH * HID * sizeof(float),
                    cudaMemcpyDeviceToDevice);

    setup_all<<<(BATCH * HID + 255) / 256, 256>>>(h, W1, W2, W3, bt);

    const dim3 g1(HID2 / BN, BATCH / BM);  // (16, 64) = 1024 CTAs
    const dim3 g2(HID2 / BN, BATCH / BM);  // (16, 64) = 1024 CTAs
    const dim3 g3(HID  / BN, BATCH / BM);  // (8, 64)  = 512 CTAs

    const float dt = 0.1f;
    for (int s = 0; s < NSTEPS; s++) {
        const float t0 = (float)s * dt;
        const float tnext[4] = {t0 + 0.05f, t0 + 0.05f, t0 + 0.1f, t0 + 0.1f};
        for (int st = 1; st <= 4; st++) {
            gemm_mma<0><<<g1, NTH, SMEM_BYTES>>>(ainh, ainl, w1h, w1l, b1,
                                                 HID, HID2, HID / BK,
                                                 x1h, x1l,
                                                 nullptr, nullptr, nullptr, nullptr,
                                                 nullptr, nullptr, 0.0f, 0);
            gemm_mma<0><<<g2, NTH, SMEM_BYTES>>>(x1h, x1l, w2h, w2l, b2,
                                                 HID2, HID2, HID2 / BK,
                                                 x2h, x2l,
                                                 nullptr, nullptr, nullptr, nullptr,
                                                 nullptr, nullptr, 0.0f, 0);
            gemm_mma<1><<<g3, NTH, SMEM_BYTES>>>(x2h, x2l, w3h, w3l, b3,
                                                 HID2, HID, HID2 / BK,
                                                 nullptr, nullptr,
                                                 state, kacc, ainh, ainl,
                                                 Wt, bt, tnext[st - 1], st);
        }
    }
}